// round 2
// baseline (speedup 1.0000x reference)
#include <cuda_runtime.h>
#include <cstdint>

// ============================================================================
// Problem constants  (784 = 49 * 16 exactly -> no K padding needed)
// ============================================================================
#define KDIM      784
#define KCH       16          // K per pipeline chunk
#define NCHUNK    49          // KDIM / KCH
#define MT        128         // M tile per CTA
#define NT        128         // N tile (full hidden width)
#define NSTAGES   4
#define THREADS   256

// Shared tile pitch: 20 floats/row -> 80 B (16B-aligned for cp.async) and the
// fragment access pattern (m in 0..7 step rows, k in 0..3 (+4)) hits all 32
// banks exactly once (m*20 mod 32 = {0,20,8,28,16,4,24,12}).
#define PITCH     20
#define STAGE_F   (2 * MT * PITCH)        // floats per stage (A then B) = 5120
#define PH        130                      // h staging pitch (floats)

// smem float offsets
#define OF_PIPE   0                        // 4*5120 = 20480 floats (81920 B); overlaid by h (128*130=16640 floats)
#define OF_PART   20480                    // 256*10
#define OF_OUTS   23040                    // 1280
#define OF_W2     24320                    // 1280
#define OF_B1     25600                    // 128
#define OF_B2     25728                    // 16 (10 used)
#define SMEM_FLOATS 25744
#define SMEM_BYTES  (SMEM_FLOATS * 4)      // 102976

// W_eff transposed: g_Wt[n*784 + k] = W_eff[k][n], tf32-RNA-rounded
__device__ __align__(16) float g_Wt[NT * KDIM];

// ============================================================================
// helpers (all baseline sm_80/90 PTX, no 'a'-suffix features)
// ============================================================================
__device__ __forceinline__ uint32_t smem_u32(const void* p) {
    uint32_t a;
    asm("{ .reg .u64 t; cvta.to.shared.u64 t, %1; cvt.u32.u64 %0, t; }" : "=r"(a) : "l"(p));
    return a;
}
__device__ __forceinline__ uint32_t f2tf32(float f) {
    uint32_t r;
    asm("cvt.rna.tf32.f32 %0, %1;" : "=r"(r) : "f"(f));
    return r;
}
__device__ __forceinline__ void cp_async16(uint32_t dst_smem, const void* src) {
    asm volatile("cp.async.cg.shared.global [%0], [%1], 16;" :: "r"(dst_smem), "l"(src) : "memory");
}
__device__ __forceinline__ void cp_commit() {
    asm volatile("cp.async.commit_group;" ::: "memory");
}
__device__ __forceinline__ void cp_wait2() {
    asm volatile("cp.async.wait_group 2;" ::: "memory");
}
__device__ __forceinline__ void mma_tf32(float* c, const uint32_t* a, const uint32_t* b) {
    asm volatile("mma.sync.aligned.m16n8k8.row.col.f32.tf32.tf32.f32 "
                 "{%0,%1,%2,%3}, {%4,%5,%6,%7}, {%8,%9}, {%0,%1,%2,%3};"
                 : "+f"(c[0]), "+f"(c[1]), "+f"(c[2]), "+f"(c[3])
                 : "r"(a[0]), "r"(a[1]), "r"(a[2]), "r"(a[3]), "r"(b[0]), "r"(b[1]));
}

// ============================================================================
// Prep kernel: W_eff^T = (conv ⊗ w1), tf32-RNA rounded (exact under HW trunc)
// ============================================================================
__global__ void prep_kernel(const float* __restrict__ conv_w, const float* __restrict__ w1) {
    int idx = blockIdx.x * blockDim.x + threadIdx.x;
    if (idx >= NT * KDIM) return;
    int n = idx / KDIM;
    int k = idx - n * KDIM;
    int i = k / 28, j = k - (k / 28) * 28;
    float v = 0.f;
    #pragma unroll
    for (int dy = 0; dy < 3; ++dy) {
        int r = i - dy;
        if (r < 0 || r >= 26) continue;
        #pragma unroll
        for (int dx = 0; dx < 3; ++dx) {
            int c = j - dx;
            if (c < 0 || c >= 26) continue;
            v += conv_w[dy * 3 + dx] * w1[(r * 26 + c) * 128 + n];
        }
    }
    g_Wt[idx] = __uint_as_float(f2tf32(v));
}

// ============================================================================
// Main fused kernel: out = relu(x @ W_eff + b1) @ w2 + b2
// ============================================================================
__global__ void __launch_bounds__(THREADS, 2)
fused_mlp_kernel(const float* __restrict__ x, const float* __restrict__ b1,
                 const float* __restrict__ w2, const float* __restrict__ b2,
                 float* __restrict__ out, int Brows) {
    extern __shared__ float sm[];
    const int tid  = threadIdx.x;
    const int wid  = tid >> 5;
    const int lane = tid & 31;
    const int tg   = lane >> 2;          // 0..7
    const int tk   = lane & 3;           // 0..3
    const int mw   = (wid >> 1) * 32;    // warp M offset (4 warps in M)
    const int nw   = (wid & 1) * 64;     // warp N offset (2 warps in N)
    const int m0   = blockIdx.x * MT;

    // constants into smem
    for (int i = tid; i < 1280; i += THREADS) sm[OF_W2 + i] = w2[i];
    if (tid < 128) sm[OF_B1 + tid] = b1[tid];
    if (tid < 10)  sm[OF_B2 + tid] = b2[tid];

    const uint32_t pipe_sm = smem_u32(sm + OF_PIPE);

    // ---- producer helper: issue one chunk into a stage (4 cp.async/thread) ----
    auto issue = [&](int c, int stage) {
        const uint32_t As = pipe_sm + (uint32_t)stage * (STAGE_F * 4);
        const uint32_t Bs = As + MT * PITCH * 4;
        #pragma unroll
        for (int r = 0; r < 2; ++r) {
            int j = tid + r * THREADS;           // 0..511
            int row = j >> 2, q = j & 3;         // row 0..127, q 0..3
            int msrc = m0 + row; if (msrc >= Brows) msrc = Brows - 1;  // clamp (tail safety)
            cp_async16(As + (uint32_t)(row * PITCH + q * 4) * 4,
                       x + (size_t)msrc * KDIM + c * KCH + q * 4);
            cp_async16(Bs + (uint32_t)(row * PITCH + q * 4) * 4,
                       g_Wt + (size_t)row * KDIM + c * KCH + q * 4);
        }
    };

    float acc[2][8][4];
    #pragma unroll
    for (int mi = 0; mi < 2; ++mi)
        #pragma unroll
        for (int ni = 0; ni < 8; ++ni)
            #pragma unroll
            for (int e = 0; e < 4; ++e) acc[mi][ni][e] = 0.f;

    // prologue: fill 3 stages
    #pragma unroll
    for (int c = 0; c < NSTAGES - 1; ++c) { issue(c, c); cp_commit(); }

    // ---- mainloop ----
    for (int c = 0; c < NCHUNK; ++c) {
        cp_wait2();
        __syncthreads();

        const int cn = c + NSTAGES - 1;
        if (cn < NCHUNK) issue(cn, cn & (NSTAGES - 1));
        cp_commit();

        const float* As = sm + OF_PIPE + (c & (NSTAGES - 1)) * STAGE_F;
        const float* Bs = As + MT * PITCH;

        #pragma unroll
        for (int ks = 0; ks < KCH; ks += 8) {
            uint32_t a[2][4];
            #pragma unroll
            for (int mi = 0; mi < 2; ++mi) {
                const int r = mw + mi * 16 + tg;
                a[mi][0] = f2tf32(As[r * PITCH + ks + tk]);
                a[mi][1] = f2tf32(As[(r + 8) * PITCH + ks + tk]);
                a[mi][2] = f2tf32(As[r * PITCH + ks + tk + 4]);
                a[mi][3] = f2tf32(As[(r + 8) * PITCH + ks + tk + 4]);
            }
            uint32_t b[8][2];
            #pragma unroll
            for (int ni = 0; ni < 8; ++ni) {
                const int n = nw + ni * 8 + tg;
                b[ni][0] = __float_as_uint(Bs[n * PITCH + ks + tk]);      // pre-rounded: trunc exact
                b[ni][1] = __float_as_uint(Bs[n * PITCH + ks + tk + 4]);
            }
            #pragma unroll
            for (int mi = 0; mi < 2; ++mi)
                #pragma unroll
                for (int ni = 0; ni < 8; ++ni)
                    mma_tf32(acc[mi][ni], a[mi], b[ni]);
        }
    }

    // ---- epilogue: h = relu(acc + b1) into smem (overlays pipeline region) ----
    __syncthreads();   // everyone done reading tiles before overlay
    {
        float* h = sm + OF_PIPE;   // [128][PH]
        #pragma unroll
        for (int mi = 0; mi < 2; ++mi) {
            #pragma unroll
            for (int ni = 0; ni < 8; ++ni) {
                const int r = mw + mi * 16 + tg;
                const int n = nw + ni * 8 + 2 * tk;
                const float bn0 = sm[OF_B1 + n], bn1 = sm[OF_B1 + n + 1];
                h[r * PH + n]           = fmaxf(acc[mi][ni][0] + bn0, 0.f);
                h[r * PH + n + 1]       = fmaxf(acc[mi][ni][1] + bn1, 0.f);
                h[(r + 8) * PH + n]     = fmaxf(acc[mi][ni][2] + bn0, 0.f);
                h[(r + 8) * PH + n + 1] = fmaxf(acc[mi][ni][3] + bn1, 0.f);
            }
        }
    }
    __syncthreads();

    // ---- GEMM2: split-K over 2 threads/row ----
    {
        const float* h = sm + OF_PIPE;
        const int row  = tid & 127;
        const int half = tid >> 7;
        float o[10];
        #pragma unroll
        for (int n = 0; n < 10; ++n) o[n] = 0.f;
        #pragma unroll 8
        for (int k = half * 64; k < half * 64 + 64; ++k) {
            const float t = h[row * PH + k];
            const float* wr = sm + OF_W2 + k * 10;
            #pragma unroll
            for (int n = 0; n < 10; ++n) o[n] = fmaf(t, wr[n], o[n]);
        }
        #pragma unroll
        for (int n = 0; n < 10; ++n) sm[OF_PART + tid * 10 + n] = o[n];
    }
    __syncthreads();
    if (tid < 128) {
        #pragma unroll
        for (int n = 0; n < 10; ++n)
            sm[OF_OUTS + tid * 10 + n] = sm[OF_PART + tid * 10 + n]
                                       + sm[OF_PART + (tid + 128) * 10 + n]
                                       + sm[OF_B2 + n];
    }
    __syncthreads();

    // ---- coalesced store ----
    const int nvalid = (Brows - m0 < MT) ? (Brows - m0) : MT;
    if (nvalid == MT) {
        float4* dst = (float4*)(out + (size_t)m0 * 10);
        const float4* src = (const float4*)(sm + OF_OUTS);
        for (int i = tid; i < MT * 10 / 4; i += THREADS) dst[i] = src[i];
    } else {
        for (int i = tid; i < nvalid * 10; i += THREADS) out[(size_t)m0 * 10 + i] = sm[OF_OUTS + i];
    }
}

// ============================================================================
// Host launch
// ============================================================================
extern "C" void kernel_launch(void* const* d_in, const int* in_sizes, int n_in,
                              void* d_out, int out_size) {
    const float* x      = (const float*)d_in[0];
    const float* conv_w = (const float*)d_in[1];
    const float* w1     = (const float*)d_in[2];
    const float* b1     = (const float*)d_in[3];
    const float* w2     = (const float*)d_in[4];
    const float* b2     = (const float*)d_in[5];
    float* out          = (float*)d_out;
    const int Brows     = in_sizes[0] / KDIM;

    static int configured = 0;
    if (!configured) {
        cudaFuncSetAttribute(fused_mlp_kernel, cudaFuncAttributeMaxDynamicSharedMemorySize, SMEM_BYTES);
        configured = 1;
    }

    prep_kernel<<<(NT * KDIM + 255) / 256, 256>>>(conv_w, w1);

    const int grid = (Brows + MT - 1) / MT;
    fused_mlp_kernel<<<grid, THREADS, SMEM_BYTES>>>(x, b1, w2, b2, out, Brows);
}